// round 9
// baseline (speedup 1.0000x reference)
#include <cuda_runtime.h>

// Problem shapes (fixed)
#define BB 16
#define TT 256
#define NPTS 2048
#define NF (NPTS * 3)            // 6144 floats per frame-row
#define NC4 (NF / 4)             // 1536 float4-chunks per frame-row
#define TC 8                     // chunks over T
#define FR (TT / TC)             // 32 frames per thread
#define NSLOTS (BB * TC)         // 128
#define BLK 128
#define NTHREADS (NSLOTS * NC4)  // 196608
#define NBLK (NTHREADS / BLK)    // 1536
#define NSTAT 5                  // cnt, sum_p, sumsq_p, sum_g, sumsq_g (per channel)
#define NCOL4 (NSTAT * NC4)      // 7680 float4 columns in scratch/g_red
#define RED_BLK 128
#define RED_GRID (NCOL4 / RED_BLK)   // 60

typedef unsigned long long ull;

// Device globals (no runtime allocation)
__device__ float    g_scratch[NSLOTS * NSTAT * NF];   // 15.7 MB per-slot partials
__device__ float    g_bsum[NBLK * 3];                 // per-block recon/temporal/nvel
__device__ float    g_red[NSTAT * NF];                // slot-reduced stats
__device__ unsigned g_done;                           // tail completion counter (reset each run)

// ---- packed f32x2 helpers (sm_103a) --------------------------------------
__device__ __forceinline__ ull f2_mul(ull a, ull b) {
    ull d; asm("mul.rn.f32x2 %0,%1,%2;" : "=l"(d) : "l"(a), "l"(b)); return d;
}
__device__ __forceinline__ ull f2_add(ull a, ull b) {
    ull d; asm("add.rn.f32x2 %0,%1,%2;" : "=l"(d) : "l"(a), "l"(b)); return d;
}
__device__ __forceinline__ ull f2_fma(ull a, ull b, ull c) {
    ull d; asm("fma.rn.f32x2 %0,%1,%2,%3;" : "=l"(d) : "l"(a), "l"(b), "l"(c)); return d;
}
__device__ __forceinline__ ull f2_pack(float a, float b) {
    ull r; asm("mov.b64 %0,{%1,%2};" : "=l"(r) : "f"(a), "f"(b)); return r;
}
__device__ __forceinline__ float f2_sum(ull v) {
    float x, y; asm("mov.b64 {%0,%1},%2;" : "=f"(x), "=f"(y) : "l"(v)); return x + y;
}
#define F2_NEG(v) ((v) ^ 0x8000000080000000ULL)
#define D2U(x) __double_as_longlong(x)
#define U2D(x) __longlong_as_double(x)

// ---------------------------------------------------------------------------
// K1: streaming pass (round-7 structure, TC=8 for 2x grid parallelism).
// thread <-> (slot, c4): owns 4 consecutive floats of every frame-row in its
// T-chunk; all pred/gt loads lane-contiguous LDG.64.
// ---------------------------------------------------------------------------
__global__ __launch_bounds__(BLK)
void k_main(const float* __restrict__ pred, const float* __restrict__ gt,
            const float* __restrict__ vis) {
    const unsigned tid  = blockIdx.x * BLK + threadIdx.x;
    const unsigned c4   = tid % NC4;           // chunk within frame-row
    const unsigned slot = tid / NC4;           // 0..NSLOTS-1
    const unsigned b    = slot / TC;
    const unsigned t0   = (slot % TC) * FR;

    const unsigned phi = c4 % 3;
    const unsigned pA  = (4 * c4) / 3;
    const unsigned pB  = pA + 1;
    const bool s1 = (phi == 2);
    const bool s2 = (phi >= 1);

    const float w0 = ((phi + 0) % 3 == 2) ? 2.f : 1.f;
    const float w1 = ((phi + 1) % 3 == 2) ? 2.f : 1.f;
    const float w2 = ((phi + 2) % 3 == 2) ? 2.f : 1.f;
    const float w3 = ((phi + 3) % 3 == 2) ? 2.f : 1.f;
    const ull cw_lo = f2_pack(w0, w1);
    const ull cw_hi = f2_pack(w2, w3);

    const double2* __restrict__ pred2 = (const double2*)pred;
    const double2* __restrict__ gt2   = (const double2*)gt;

    ull spx0 = 0, spx1 = 0, spq0 = 0, spq1 = 0;
    ull sgx0 = 0, sgx1 = 0, sgq0 = 0, sgq1 = 0;
    ull cnt0 = 0, cnt1 = 0;
    ull recon2 = 0, temp2 = 0, nvel2 = 0;

    ull ndplo = 0, ndphi = 0, pmlo = 0, pmhi = 0;

    if (t0 > 0) {  // preload frame t0-1
        unsigned o4 = (b * TT + t0 - 1) * NC4 + c4;
        unsigned ov = (b * TT + t0 - 1) * NPTS;
        double2 p = pred2[o4], g = gt2[o4];
        float vA = vis[ov + pA], vB = vis[ov + pB];
        float mA = (vA > 0.5f) ? 1.f : 0.f;
        float mB = (vB > 0.5f) ? 1.f : 0.f;
        pmlo = f2_pack(mA, s1 ? mB : mA);
        pmhi = f2_pack(s2 ? mB : mA, mB);
        ndplo = f2_add(D2U(g.x), F2_NEG(D2U(p.x)));
        ndphi = f2_add(D2U(g.y), F2_NEG(D2U(p.y)));
    }

    unsigned o4 = (b * TT + t0) * NC4 + c4;
    unsigned ov = (b * TT + t0) * NPTS;

    #pragma unroll 4
    for (unsigned i = 0; i < FR; i++) {
        double2 p = pred2[o4], g = gt2[o4];
        float vA = vis[ov + pA], vB = vis[ov + pB];
        o4 += NC4; ov += NPTS;

        float mA = (vA > 0.5f) ? 1.f : 0.f;
        float mB = (vB > 0.5f) ? 1.f : 0.f;
        ull mmlo = f2_pack(mA, s1 ? mB : mA);
        ull mmhi = f2_pack(s2 ? mB : mA, mB);

        ull plo = D2U(p.x), phi_ = D2U(p.y);
        ull glo = D2U(g.x), ghi_ = D2U(g.y);

        ull mp = f2_mul(mmlo, plo);
        spx0 = f2_add(spx0, mp);  spq0 = f2_fma(mp, plo, spq0);
        mp = f2_mul(mmhi, phi_);
        spx1 = f2_add(spx1, mp);  spq1 = f2_fma(mp, phi_, spq1);
        mp = f2_mul(mmlo, glo);
        sgx0 = f2_add(sgx0, mp);  sgq0 = f2_fma(mp, glo, sgq0);
        mp = f2_mul(mmhi, ghi_);
        sgx1 = f2_add(sgx1, mp);  sgq1 = f2_fma(mp, ghi_, sgq1);
        cnt0 = f2_add(cnt0, mmlo);
        cnt1 = f2_add(cnt1, mmhi);

        ull dlo = f2_add(plo, F2_NEG(glo));
        ull dhi = f2_add(phi_, F2_NEG(ghi_));
        ull dmlo = f2_mul(dlo, mmlo);
        ull dmhi = f2_mul(dhi, mmhi);
        recon2 = f2_fma(f2_mul(dmlo, cw_lo), dmlo, recon2);
        recon2 = f2_fma(f2_mul(dmhi, cw_hi), dmhi, recon2);

        ull elo = f2_add(dlo, ndplo);
        ull ehi = f2_add(dhi, ndphi);
        ull vmlo = f2_mul(mmlo, pmlo);
        ull vmhi = f2_mul(mmhi, pmhi);
        temp2 = f2_fma(f2_mul(elo, vmlo), elo, temp2);
        temp2 = f2_fma(f2_mul(ehi, vmhi), ehi, temp2);
        nvel2 = f2_add(nvel2, vmlo);
        nvel2 = f2_add(nvel2, vmhi);    // triple-counts each point -> /3 later

        ndplo = F2_NEG(dlo); ndphi = F2_NEG(dhi);
        pmlo = mmlo; pmhi = mmhi;
    }

    // per-channel partials -> scratch (coalesced 16B stores per stat)
    {
        double2* s = (double2*)g_scratch;
        unsigned base = slot * (NSTAT * NC4) + c4;   // double2 index
        double2 v;
        v.x = U2D(cnt0); v.y = U2D(cnt1); s[base]           = v;
        v.x = U2D(spx0); v.y = U2D(spx1); s[base + 1 * NC4] = v;
        v.x = U2D(spq0); v.y = U2D(spq1); s[base + 2 * NC4] = v;
        v.x = U2D(sgx0); v.y = U2D(sgx1); s[base + 3 * NC4] = v;
        v.x = U2D(sgq0); v.y = U2D(sgq1); s[base + 4 * NC4] = v;
    }

    // block-reduce recon/temporal/nvel -> per-block partial (no atomics)
    float wr = f2_sum(recon2), wt = f2_sum(temp2), wv = f2_sum(nvel2);
    __shared__ float sm[4][3];
    #pragma unroll
    for (int o = 16; o > 0; o >>= 1) {
        wr += __shfl_down_sync(0xffffffffu, wr, o);
        wt += __shfl_down_sync(0xffffffffu, wt, o);
        wv += __shfl_down_sync(0xffffffffu, wv, o);
    }
    int lane = threadIdx.x & 31, wid = threadIdx.x >> 5;
    if (lane == 0) { sm[wid][0] = wr; sm[wid][1] = wt; sm[wid][2] = wv; }
    __syncthreads();
    if (threadIdx.x < 3) {
        int k = threadIdx.x;
        g_bsum[blockIdx.x * 3 + k] = sm[0][k] + sm[1][k] + sm[2][k] + sm[3][k];
    }
}

// ---------------------------------------------------------------------------
// K2 (fused tail): phase A = 60 blocks fold the 128 slots (L2-resident
// scratch, float4 columns). Last-done block (threadfence + counter) runs
// phase B: per-point identity + g_bsum fold + adaptive re-weighting, then
// resets the counter for the next graph replay. Deterministic: partitions
// are fixed and phase B runs in one block.
// ---------------------------------------------------------------------------
__global__ __launch_bounds__(RED_BLK)
void k_tail(float* __restrict__ out) {
    const unsigned j = blockIdx.x * RED_BLK + threadIdx.x;   // float4 column
    const float4* s4 = (const float4*)g_scratch;
    float4 acc = make_float4(0.f, 0.f, 0.f, 0.f);
    #pragma unroll 8
    for (int slot = 0; slot < NSLOTS; slot++) {
        float4 v = s4[(unsigned)slot * NCOL4 + j];
        acc.x += v.x; acc.y += v.y; acc.z += v.z; acc.w += v.w;
    }
    ((float4*)g_red)[j] = acc;

    // threadFenceReduction pattern: fence all threads' stores, then one atomic
    __threadfence();
    __syncthreads();
    __shared__ unsigned is_last;
    if (threadIdx.x == 0) {
        unsigned old = atomicAdd(&g_done, 1u);
        is_last = (old == RED_GRID - 1) ? 1u : 0u;
    }
    __syncthreads();
    if (!is_last) return;
    __threadfence();   // acquire side

    // ---- phase B (one block, 128 threads) --------------------------------
    const int tid = threadIdx.x;

    float ident = 0.f, cntsum = 0.f;
    for (int n = tid; n < NPTS; n += RED_BLK) {
        float c  = __ldcg(&g_red[3 * n]);             // per-point visible count
        float dm = fmaxf(c, 1.f);
        float dv = fmaxf(c - 1.f, 1.f);
        float num = 0.f, den = 0.f;
        #pragma unroll
        for (int k = 0; k < 3; k++) {
            int ch = 3 * n + k;
            float sx = __ldcg(&g_red[1 * NF + ch]);
            float sq = __ldcg(&g_red[2 * NF + ch]);
            float mean = sx / dm;
            float pv = (sq - 2.f * mean * sx + c * mean * mean) / dv;
            float gx = __ldcg(&g_red[3 * NF + ch]);
            float gq = __ldcg(&g_red[4 * NF + ch]);
            float gmean = gx / dm;
            float gv = (gq - 2.f * gmean * gx + c * gmean * gmean) / dv;
            num += fabsf(pv - gv);
            den += gv;
        }
        float vr = num / (den + 1e-6f);
        ident  += (c > 1.f) ? vr : 0.f;
        cntsum += c;
    }

    double racc = 0.0, tacc = 0.0, vacc = 0.0;
    for (int jb = tid; jb < NBLK; jb += RED_BLK) {
        racc += (double)g_bsum[jb * 3 + 0];
        tacc += (double)g_bsum[jb * 3 + 1];
        vacc += (double)g_bsum[jb * 3 + 2];
    }

    // block reduction of 5 quantities over 4 warps
    __shared__ double sr[5][4];
    double di = (double)ident, dc = (double)cntsum;
    #pragma unroll
    for (int o = 16; o > 0; o >>= 1) {
        di   += __shfl_down_sync(0xffffffffu, di, o);
        dc   += __shfl_down_sync(0xffffffffu, dc, o);
        racc += __shfl_down_sync(0xffffffffu, racc, o);
        tacc += __shfl_down_sync(0xffffffffu, tacc, o);
        vacc += __shfl_down_sync(0xffffffffu, vacc, o);
    }
    int lane = tid & 31, wid = tid >> 5;
    if (lane == 0) {
        sr[0][wid] = di; sr[1][wid] = dc; sr[2][wid] = racc;
        sr[3][wid] = tacc; sr[4][wid] = vacc;
    }
    __syncthreads();
    if (tid == 0) {
        di   = sr[0][0] + sr[0][1] + sr[0][2] + sr[0][3];
        dc   = sr[1][0] + sr[1][1] + sr[1][2] + sr[1][3];
        racc = sr[2][0] + sr[2][1] + sr[2][2] + sr[2][3];
        tacc = sr[3][0] + sr[3][1] + sr[3][2] + sr[3][3];
        vacc = sr[4][0] + sr[4][1] + sr[4][2] + sr[4][3];

        double nvis = dc;
        double nvel = vacc / 3.0;    // channels triple-count each point
        float recon    = (nvis > 0.0) ? (float)(racc / fmax(nvis, 1.0)) : 0.f;
        float temporal = (nvel > 0.0) ? (float)(tacc / fmax(nvel, 1.0)) : 0.f;
        float identity = (float)(di / (double)NPTS);

        float rl = recon, tl = temporal, il = identity;
        bool  all_pos = (rl > 0.f) && (tl > 0.f) && (il > 0.f);
        float mx     = fmaxf(fmaxf(rl, tl), il);
        float target = mx / 3.f;
        float thresh = 10.f * target;

        float rw = (all_pos && rl > thresh) ? 1.0f * target / fmaxf(rl, 1e-30f) : 1.0f;
        float tw = (all_pos && tl > thresh) ? 0.5f * target / fmaxf(tl, 1e-30f) : 0.5f;
        float iw = (all_pos && il > thresh) ? 0.1f * target / fmaxf(il, 1e-30f) : 0.1f;

        out[0] = rw * recon + tw * temporal + iw * identity;
        out[1] = recon;
        out[2] = temporal;
        out[3] = identity;

        g_done = 0;   // reset for next graph replay
    }
}

extern "C" void kernel_launch(void* const* d_in, const int* in_sizes, int n_in,
                              void* d_out, int out_size) {
    const float* pred = (const float*)d_in[0];
    const float* gt   = (const float*)d_in[1];
    const float* vis  = (const float*)d_in[2];
    float* out = (float*)d_out;

    k_main<<<NBLK, BLK>>>(pred, gt, vis);
    k_tail<<<RED_GRID, RED_BLK>>>(out);
}

// round 10
// speedup vs baseline: 1.3712x; 1.3712x over previous
#include <cuda_runtime.h>

// Problem shapes (fixed)
#define BB 16
#define TT 256
#define NPTS 2048
#define NF (NPTS * 3)            // 6144 floats per frame-row
#define NC4 (NF / 4)             // 1536 float4-chunks per frame-row
#define TC 8                     // chunks over T
#define FR (TT / TC)             // 32 frames per thread
#define NSLOTS (BB * TC)         // 128
#define BLK 128
#define NTHREADS (NSLOTS * NC4)  // 196608
#define NBLK (NTHREADS / BLK)    // 1536 main-pass blocks
#define NSTAT 5                  // cnt, sum_p, sumsq_p, sum_g, sumsq_g (per channel)
#define NCOLS (NSTAT * NF)       // 30720 scalar columns in scratch
// tail layout
#define TBLK 256
#define NRED (NCOLS / TBLK)      // 120 reduce blocks
#define TGRID (NRED + 1)         // +1 bsum-fold block

typedef unsigned long long ull;

// Device globals (no runtime allocation)
__device__ float    g_scratch[NSLOTS * NCOLS];  // 15.7 MB per-slot partials
__device__ float    g_bsum[NBLK * 3];           // per-block recon/temporal/nvel
__device__ float    g_red[NCOLS];               // slot-reduced stats
__device__ double   g_psum[3];                  // folded recon/temporal/nvel
__device__ unsigned g_done;                     // completion counter (reset each run)

// ---- packed f32x2 helpers (sm_103a) --------------------------------------
__device__ __forceinline__ ull f2_mul(ull a, ull b) {
    ull d; asm("mul.rn.f32x2 %0,%1,%2;" : "=l"(d) : "l"(a), "l"(b)); return d;
}
__device__ __forceinline__ ull f2_add(ull a, ull b) {
    ull d; asm("add.rn.f32x2 %0,%1,%2;" : "=l"(d) : "l"(a), "l"(b)); return d;
}
__device__ __forceinline__ ull f2_fma(ull a, ull b, ull c) {
    ull d; asm("fma.rn.f32x2 %0,%1,%2,%3;" : "=l"(d) : "l"(a), "l"(b), "l"(c)); return d;
}
__device__ __forceinline__ ull f2_pack(float a, float b) {
    ull r; asm("mov.b64 %0,{%1,%2};" : "=l"(r) : "f"(a), "f"(b)); return r;
}
__device__ __forceinline__ float f2_sum(ull v) {
    float x, y; asm("mov.b64 {%0,%1},%2;" : "=f"(x), "=f"(y) : "l"(v)); return x + y;
}
#define F2_NEG(v) ((v) ^ 0x8000000080000000ULL)
#define D2U(x) __double_as_longlong(x)
#define U2D(x) __longlong_as_double(x)

// ---------------------------------------------------------------------------
// K1: streaming pass (proven round-9 structure: TC=8, 128-thr blocks, no reg
// cap). thread <-> (slot, c4); all pred/gt loads lane-contiguous LDG.64 with
// .cs streaming hint (evict-first: keeps L2 for the scratch the tail reads).
// ---------------------------------------------------------------------------
__global__ __launch_bounds__(BLK)
void k_main(const float* __restrict__ pred, const float* __restrict__ gt,
            const float* __restrict__ vis) {
    const unsigned tid  = blockIdx.x * BLK + threadIdx.x;
    const unsigned c4   = tid % NC4;           // chunk within frame-row
    const unsigned slot = tid / NC4;           // 0..NSLOTS-1
    const unsigned b    = slot / TC;
    const unsigned t0   = (slot % TC) * FR;

    const unsigned phi = c4 % 3;
    const unsigned pA  = (4 * c4) / 3;
    const unsigned pB  = pA + 1;
    const bool s1 = (phi == 2);
    const bool s2 = (phi >= 1);

    const float w0 = ((phi + 0) % 3 == 2) ? 2.f : 1.f;
    const float w1 = ((phi + 1) % 3 == 2) ? 2.f : 1.f;
    const float w2 = ((phi + 2) % 3 == 2) ? 2.f : 1.f;
    const float w3 = ((phi + 3) % 3 == 2) ? 2.f : 1.f;
    const ull cw_lo = f2_pack(w0, w1);
    const ull cw_hi = f2_pack(w2, w3);

    const double2* __restrict__ pred2 = (const double2*)pred;
    const double2* __restrict__ gt2   = (const double2*)gt;

    ull spx0 = 0, spx1 = 0, spq0 = 0, spq1 = 0;
    ull sgx0 = 0, sgx1 = 0, sgq0 = 0, sgq1 = 0;
    ull cnt0 = 0, cnt1 = 0;
    ull recon2 = 0, temp2 = 0, nvel2 = 0;

    ull ndplo = 0, ndphi = 0, pmlo = 0, pmhi = 0;

    if (t0 > 0) {  // preload frame t0-1
        unsigned o4 = (b * TT + t0 - 1) * NC4 + c4;
        unsigned ov = (b * TT + t0 - 1) * NPTS;
        double2 p = __ldcs(&pred2[o4]), g = __ldcs(&gt2[o4]);
        float vA = __ldcs(&vis[ov + pA]), vB = __ldcs(&vis[ov + pB]);
        float mA = (vA > 0.5f) ? 1.f : 0.f;
        float mB = (vB > 0.5f) ? 1.f : 0.f;
        pmlo = f2_pack(mA, s1 ? mB : mA);
        pmhi = f2_pack(s2 ? mB : mA, mB);
        ndplo = f2_add(D2U(g.x), F2_NEG(D2U(p.x)));
        ndphi = f2_add(D2U(g.y), F2_NEG(D2U(p.y)));
    }

    unsigned o4 = (b * TT + t0) * NC4 + c4;
    unsigned ov = (b * TT + t0) * NPTS;

    #pragma unroll 4
    for (unsigned i = 0; i < FR; i++) {
        double2 p = __ldcs(&pred2[o4]), g = __ldcs(&gt2[o4]);
        float vA = __ldcs(&vis[ov + pA]), vB = __ldcs(&vis[ov + pB]);
        o4 += NC4; ov += NPTS;

        float mA = (vA > 0.5f) ? 1.f : 0.f;
        float mB = (vB > 0.5f) ? 1.f : 0.f;
        ull mmlo = f2_pack(mA, s1 ? mB : mA);
        ull mmhi = f2_pack(s2 ? mB : mA, mB);

        ull plo = D2U(p.x), phi_ = D2U(p.y);
        ull glo = D2U(g.x), ghi_ = D2U(g.y);

        ull mp = f2_mul(mmlo, plo);
        spx0 = f2_add(spx0, mp);  spq0 = f2_fma(mp, plo, spq0);
        mp = f2_mul(mmhi, phi_);
        spx1 = f2_add(spx1, mp);  spq1 = f2_fma(mp, phi_, spq1);
        mp = f2_mul(mmlo, glo);
        sgx0 = f2_add(sgx0, mp);  sgq0 = f2_fma(mp, glo, sgq0);
        mp = f2_mul(mmhi, ghi_);
        sgx1 = f2_add(sgx1, mp);  sgq1 = f2_fma(mp, ghi_, sgq1);
        cnt0 = f2_add(cnt0, mmlo);
        cnt1 = f2_add(cnt1, mmhi);

        ull dlo = f2_add(plo, F2_NEG(glo));
        ull dhi = f2_add(phi_, F2_NEG(ghi_));
        ull dmlo = f2_mul(dlo, mmlo);
        ull dmhi = f2_mul(dhi, mmhi);
        recon2 = f2_fma(f2_mul(dmlo, cw_lo), dmlo, recon2);
        recon2 = f2_fma(f2_mul(dmhi, cw_hi), dmhi, recon2);

        ull elo = f2_add(dlo, ndplo);
        ull ehi = f2_add(dhi, ndphi);
        ull vmlo = f2_mul(mmlo, pmlo);
        ull vmhi = f2_mul(mmhi, pmhi);
        temp2 = f2_fma(f2_mul(elo, vmlo), elo, temp2);
        temp2 = f2_fma(f2_mul(ehi, vmhi), ehi, temp2);
        nvel2 = f2_add(nvel2, vmlo);
        nvel2 = f2_add(nvel2, vmhi);    // triple-counts each point -> /3 later

        ndplo = F2_NEG(dlo); ndphi = F2_NEG(dhi);
        pmlo = mmlo; pmhi = mmhi;
    }

    // per-channel partials -> scratch (coalesced 16B stores per stat)
    {
        double2* s = (double2*)g_scratch;
        unsigned base = slot * (NSTAT * NC4) + c4;   // double2 index
        double2 v;
        v.x = U2D(cnt0); v.y = U2D(cnt1); s[base]           = v;
        v.x = U2D(spx0); v.y = U2D(spx1); s[base + 1 * NC4] = v;
        v.x = U2D(spq0); v.y = U2D(spq1); s[base + 2 * NC4] = v;
        v.x = U2D(sgx0); v.y = U2D(sgx1); s[base + 3 * NC4] = v;
        v.x = U2D(sgq0); v.y = U2D(sgq1); s[base + 4 * NC4] = v;
    }

    // block-reduce recon/temporal/nvel -> per-block partial (no atomics)
    float wr = f2_sum(recon2), wt = f2_sum(temp2), wv = f2_sum(nvel2);
    __shared__ float sm[4][3];
    #pragma unroll
    for (int o = 16; o > 0; o >>= 1) {
        wr += __shfl_down_sync(0xffffffffu, wr, o);
        wt += __shfl_down_sync(0xffffffffu, wt, o);
        wv += __shfl_down_sync(0xffffffffu, wv, o);
    }
    int lane = threadIdx.x & 31, wid = threadIdx.x >> 5;
    if (lane == 0) { sm[wid][0] = wr; sm[wid][1] = wt; sm[wid][2] = wv; }
    __syncthreads();
    if (threadIdx.x < 3) {
        int k = threadIdx.x;
        g_bsum[blockIdx.x * 3 + k] = sm[0][k] + sm[1][k] + sm[2][k] + sm[3][k];
    }
}

// ---------------------------------------------------------------------------
// K2 (fused tail, 121 blocks x 256):
//   blocks 0..119 : fold 128 slots, ONE SCALAR COLUMN PER THREAD (30720
//                   threads), 4 independent accumulators -> >=8 loads in
//                   flight; 15.7 MB L2-hot.
//   block  120    : fold g_bsum (1536x3) -> g_psum[3] doubles.
//   last-done block (threadfence+counter): identity over L2-hot g_red +
//                   adaptive re-weighting; resets counter for graph replay.
// Deterministic: fixed partitions, single-block phase B, fixed fold order.
// ---------------------------------------------------------------------------
__global__ __launch_bounds__(TBLK)
void k_tail(float* __restrict__ out) {
    const int tid = threadIdx.x;

    if (blockIdx.x < NRED) {
        // ---- slot fold: one scalar column per thread --------------------
        const unsigned col = blockIdx.x * TBLK + tid;
        float a0 = 0.f, a1 = 0.f, a2 = 0.f, a3 = 0.f;
        #pragma unroll 4
        for (int s = 0; s < NSLOTS; s += 4) {
            a0 += g_scratch[(unsigned)(s + 0) * NCOLS + col];
            a1 += g_scratch[(unsigned)(s + 1) * NCOLS + col];
            a2 += g_scratch[(unsigned)(s + 2) * NCOLS + col];
            a3 += g_scratch[(unsigned)(s + 3) * NCOLS + col];
        }
        g_red[col] = (a0 + a1) + (a2 + a3);
    } else {
        // ---- bsum fold: 1536 blocks x 3 -> 3 doubles --------------------
        double r = 0.0, t = 0.0, v = 0.0;
        #pragma unroll 2
        for (int jb = tid; jb < NBLK; jb += TBLK) {
            r += (double)g_bsum[jb * 3 + 0];
            t += (double)g_bsum[jb * 3 + 1];
            v += (double)g_bsum[jb * 3 + 2];
        }
        __shared__ double sb[3][8];
        #pragma unroll
        for (int o = 16; o > 0; o >>= 1) {
            r += __shfl_down_sync(0xffffffffu, r, o);
            t += __shfl_down_sync(0xffffffffu, t, o);
            v += __shfl_down_sync(0xffffffffu, v, o);
        }
        int lane = tid & 31, wid = tid >> 5;
        if (lane == 0) { sb[0][wid] = r; sb[1][wid] = t; sb[2][wid] = v; }
        __syncthreads();
        if (tid < 3) {
            double acc = 0.0;
            #pragma unroll
            for (int w = 0; w < 8; w++) acc += sb[tid][w];
            g_psum[tid] = acc;
        }
    }

    // ---- completion counter (threadFenceReduction pattern) --------------
    __threadfence();
    __syncthreads();
    __shared__ unsigned is_last;
    if (tid == 0) {
        unsigned old = atomicAdd(&g_done, 1u);
        is_last = (old == TGRID - 1) ? 1u : 0u;
    }
    __syncthreads();
    if (!is_last) return;
    __threadfence();   // acquire side

    // ---- phase B: identity + final (one block, 256 threads) -------------
    float ident = 0.f, cntsum = 0.f;
    #pragma unroll
    for (int rep = 0; rep < NPTS / TBLK; rep++) {
        int n = tid + rep * TBLK;
        float c  = __ldcg(&g_red[3 * n]);
        float dm = fmaxf(c, 1.f);
        float dv = fmaxf(c - 1.f, 1.f);
        float num = 0.f, den = 0.f;
        #pragma unroll
        for (int k = 0; k < 3; k++) {
            int ch = 3 * n + k;
            float sx = __ldcg(&g_red[1 * NF + ch]);
            float sq = __ldcg(&g_red[2 * NF + ch]);
            float mean = sx / dm;
            float pv = (sq - 2.f * mean * sx + c * mean * mean) / dv;
            float gx = __ldcg(&g_red[3 * NF + ch]);
            float gq = __ldcg(&g_red[4 * NF + ch]);
            float gmean = gx / dm;
            float gv = (gq - 2.f * gmean * gx + c * gmean * gmean) / dv;
            num += fabsf(pv - gv);
            den += gv;
        }
        float vr = num / (den + 1e-6f);
        ident  += (c > 1.f) ? vr : 0.f;
        cntsum += c;
    }

    __shared__ double sr[2][8];
    double di = (double)ident, dc = (double)cntsum;
    #pragma unroll
    for (int o = 16; o > 0; o >>= 1) {
        di += __shfl_down_sync(0xffffffffu, di, o);
        dc += __shfl_down_sync(0xffffffffu, dc, o);
    }
    int lane = tid & 31, wid = tid >> 5;
    if (lane == 0) { sr[0][wid] = di; sr[1][wid] = dc; }
    __syncthreads();
    if (tid == 0) {
        di = 0.0; dc = 0.0;
        #pragma unroll
        for (int w = 0; w < 8; w++) { di += sr[0][w]; dc += sr[1][w]; }

        double racc = g_psum[0], tacc = g_psum[1];
        double nvel = g_psum[2] / 3.0;   // channels triple-count each point
        double nvis = dc;
        float recon    = (nvis > 0.0) ? (float)(racc / fmax(nvis, 1.0)) : 0.f;
        float temporal = (nvel > 0.0) ? (float)(tacc / fmax(nvel, 1.0)) : 0.f;
        float identity = (float)(di / (double)NPTS);

        float rl = recon, tl = temporal, il = identity;
        bool  all_pos = (rl > 0.f) && (tl > 0.f) && (il > 0.f);
        float mx     = fmaxf(fmaxf(rl, tl), il);
        float target = mx / 3.f;
        float thresh = 10.f * target;

        float rw = (all_pos && rl > thresh) ? 1.0f * target / fmaxf(rl, 1e-30f) : 1.0f;
        float tw = (all_pos && tl > thresh) ? 0.5f * target / fmaxf(tl, 1e-30f) : 0.5f;
        float iw = (all_pos && il > thresh) ? 0.1f * target / fmaxf(il, 1e-30f) : 0.1f;

        out[0] = rw * recon + tw * temporal + iw * identity;
        out[1] = recon;
        out[2] = temporal;
        out[3] = identity;

        g_done = 0;   // reset for next graph replay
    }
}

extern "C" void kernel_launch(void* const* d_in, const int* in_sizes, int n_in,
                              void* d_out, int out_size) {
    const float* pred = (const float*)d_in[0];
    const float* gt   = (const float*)d_in[1];
    const float* vis  = (const float*)d_in[2];
    float* out = (float*)d_out;

    k_main<<<NBLK, BLK>>>(pred, gt, vis);
    k_tail<<<TGRID, TBLK>>>(out);
}